// round 7
// baseline (speedup 1.0000x reference)
#include <cuda_runtime.h>

#define BB 64
#define HH 56
#define WW 56
#define CC 256
#define COUT 64
#define ROUTES 4
#define RW (CC / ROUTES)          // 64 channels per route
#define RCHUNKS 14                // 4 rows per chunk
#define SLOTS 9                   // 3x3 (dh,dw) classes

// per-(batch,chunk) partial patch sums: [BB][RCHUNKS][SLOTS][CC] floats (~8 MB)
__device__ float g_S2[BB * RCHUNKS * SLOTS * CC];
__device__ int   g_cnt[BB];       // zero-initialized; self-resetting each run
__device__ int   g_route[BB];

__device__ __forceinline__ float4 f4add(float4 a, float4 b) {
    return make_float4(a.x + b.x, a.y + b.y, a.z + b.z, a.w + b.w);
}
__device__ __forceinline__ float4 f4sub(float4 a, float4 b) {
    return make_float4(a.x - b.x, a.y - b.y, a.z - b.z, a.w - b.w);
}

// ---------------------------------------------------------------------------
// K1 (fused): streaming patch-sum reduction + per-batch routing tail.
// Block = (batch, 4-row chunk), 256 threads = 64 channel-quads x 4 row-threads.
// Each row-thread owns ONE row: even/odd running float4 sums + edge captures
// give the three dw-class sums; reducer (rt==0) applies h-parity/boundary
// logic and stores 9 slots to scratch.
// The LAST block of each batch (fence+atomic counter) then sums the 14 chunk
// partials, runs the 2304x64 pooled GEMM, dense(4), argmax -> route + logits.
// ---------------------------------------------------------------------------
__global__ __launch_bounds__(256) void patch_route_kernel(const float* __restrict__ in,
                                                          const float* __restrict__ conv_w,
                                                          const float* __restrict__ conv_b,
                                                          const float* __restrict__ fc_w,
                                                          const float* __restrict__ fc_b,
                                                          float* __restrict__ out_logits) {
    const int b     = blockIdx.x;
    const int chunk = blockIdx.y;          // 0..13
    const int tid   = threadIdx.x;
    const int q     = tid & 63;            // channel quad 0..63
    const int rt    = tid >> 6;            // row-thread 0..3
    const int h     = chunk * 4 + rt;

    const float4* row = (const float4*)in
                      + ((size_t)(b * HH + h) * WW) * (CC / 4) + q;

    float4 e = make_float4(0.f, 0.f, 0.f, 0.f);
    float4 o = make_float4(0.f, 0.f, 0.f, 0.f);
    float4 v0, v54, v55;
#pragma unroll
    for (int w = 0; w < WW; w += 2) {
        float4 a  = row[(size_t)w * (CC / 4)];
        float4 bb = row[(size_t)(w + 1) * (CC / 4)];
        if (w == 0)  { v0 = a; }
        if (w == 54) { v54 = a; v55 = bb; }
        e = f4add(e, a);
        o = f4add(o, bb);
    }

    __shared__ float4 sacc[4][3][64];
    sacc[rt][0][q] = f4sub(e, v54);  // W0: even w in [0,52]
    sacc[rt][1][q] = f4sub(o, v55);  // W1: odd  w in [1,53]
    sacc[rt][2][q] = f4sub(e, v0);   // W2: even w in [2,54]
    __syncthreads();

    if (rt == 0) {
        float4 out[SLOTS];
#pragma unroll
        for (int s = 0; s < SLOTS; s++) out[s] = make_float4(0.f, 0.f, 0.f, 0.f);

#pragma unroll
        for (int r = 0; r < 4; r++) {
            const int hh = chunk * 4 + r;
            const float4 W0 = sacc[r][0][q];
            const float4 W1 = sacc[r][1][q];
            const float4 W2 = sacc[r][2][q];
            if ((hh & 1) == 0) {
                if (hh <= 52) { out[0] = f4add(out[0], W0); out[1] = f4add(out[1], W1); out[2] = f4add(out[2], W2); }
                if (hh >= 2)  { out[6] = f4add(out[6], W0); out[7] = f4add(out[7], W1); out[8] = f4add(out[8], W2); }
            } else {
                if (hh <= 53) { out[3] = f4add(out[3], W0); out[4] = f4add(out[4], W1); out[5] = f4add(out[5], W2); }
            }
        }

        float4* dst = (float4*)g_S2 + ((size_t)(b * RCHUNKS + chunk) * SLOTS) * (CC / 4) + q;
#pragma unroll
        for (int s = 0; s < SLOTS; s++)
            dst[(size_t)s * (CC / 4)] = out[s];
    }
    __syncthreads();

    // ---- per-batch completion counter; only the last block proceeds --------
    __shared__ int s_last;
    if (tid == 0) {
        __threadfence();                           // publish g_S2 stores
        int old = atomicAdd(&g_cnt[b], 1);
        s_last = (old == RCHUNKS - 1);
        if (s_last) g_cnt[b] = 0;                  // reset for next graph replay
    }
    __syncthreads();
    if (!s_last) return;
    if (tid == 0) __threadfence();                 // acquire side
    __syncthreads();

    // ---- tail: sum 14 chunk-partials -> sS(2304) ---------------------------
    __shared__ __align__(16) float sS[SLOTS * CC];
    for (int i = tid; i < SLOTS * CC / 4; i += 256) {
        float4 s = make_float4(0.f, 0.f, 0.f, 0.f);
#pragma unroll
        for (int k = 0; k < RCHUNKS; k++) {
            const float4* src = (const float4*)g_S2
                              + (size_t)(b * RCHUNKS + k) * (SLOTS * CC / 4) + i;
            s = f4add(s, __ldcg(src));             // L2 read (cross-SM producer)
        }
        ((float4*)sS)[i] = s;
    }
    __syncthreads();

    // ---- pooled GEMM: 4 sub-segments of 576 per output ---------------------
    const int oc  = tid & 63;
    const int sub = tid >> 6;
    const int j0  = sub * 576;

    float acc = 0.f;
#pragma unroll 8
    for (int j = 0; j < 576; j++)
        acc = fmaf(sS[j0 + j], conv_w[(size_t)(j0 + j) * COUT + oc], acc);

    __shared__ float part[4][COUT];
    part[sub][oc] = acc;
    __syncthreads();

    __shared__ float sp[COUT];
    __shared__ float slog[ROUTES];
    if (tid < COUT) {
        sp[tid] = (part[0][tid] + part[1][tid] + part[2][tid] + part[3][tid])
                  * (1.0f / 729.0f) + conv_b[tid];
    }
    __syncthreads();

    if (tid < ROUTES) {
        float l = fc_b[tid];
#pragma unroll
        for (int j = 0; j < COUT; j++)
            l = fmaf(sp[j], fc_w[j * ROUTES + tid], l);
        slog[tid] = l;
        out_logits[b * ROUTES + tid] = l;
    }
    __syncthreads();

    if (tid == 0) {
        float best = slog[0];
        int br = 0;
#pragma unroll
        for (int r = 1; r < ROUTES; r++)
            if (slog[r] > best) { best = slog[r]; br = r; }  // first-max == argmax
        g_route[b] = br;
    }
}

// ---------------------------------------------------------------------------
// K3: routed channel-group gather (measured-best config, LTS-capped).
// Block = (batch, 64-pixel tile), 4 independent float4 copies per thread.
// ---------------------------------------------------------------------------
__global__ __launch_bounds__(256) void gather_kernel(const float4* __restrict__ in4,
                                                     float4* __restrict__ out4) {
    const int b = blockIdx.x;
    const int r = g_route[b];
    const size_t base_pix = (size_t)b * (HH * WW) + (size_t)blockIdx.y * 64;
    const float4* src = in4 + base_pix * (CC / 4) + r * (RW / 4);
    float4* dst = out4 + base_pix * (RW / 4);

    const int t = threadIdx.x;
#pragma unroll
    for (int k = 0; k < 4; k++) {
        const int item = t + k * 256;      // 0..1023 = 64 pixels x 16 float4
        const int p = item >> 4;
        const int j = item & 15;
        dst[item] = src[(size_t)p * (CC / 4) + j];
    }
}

// ---------------------------------------------------------------------------
extern "C" void kernel_launch(void* const* d_in, const int* in_sizes, int n_in,
                              void* d_out, int out_size) {
    const float* in     = (const float*)d_in[0];
    const float* conv_w = (const float*)d_in[1];
    const float* conv_b = (const float*)d_in[2];
    const float* fc_w   = (const float*)d_in[3];
    const float* fc_b   = (const float*)d_in[4];

    float* out        = (float*)d_out;
    float* out_logits = out + (size_t)BB * HH * WW * RW;  // x first, then logits

    patch_route_kernel<<<dim3(BB, RCHUNKS), 256>>>(in, conv_w, conv_b, fc_w, fc_b, out_logits);
    gather_kernel<<<dim3(BB, HH * WW / 64), 256>>>((const float4*)in, (float4*)out);
}

// round 8
// speedup vs baseline: 1.1015x; 1.1015x over previous
#include <cuda_runtime.h>

#define BB 64
#define HH 56
#define WW 56
#define CC 256
#define COUT 64
#define ROUTES 4
#define RW (CC / ROUTES)          // 64 channels per route
#define RCHUNKS 14                // 4 rows per chunk
#define SLOTS 9                   // 3x3 (dh,dw) classes

// per-(batch,chunk) partial patch sums: [BB][RCHUNKS][SLOTS][CC] floats (~8 MB)
__device__ float g_S2[BB * RCHUNKS * SLOTS * CC];
__device__ int   g_cnt[BB];       // zero-initialized; self-resetting each run
__device__ int   g_route[BB];

__device__ __forceinline__ float4 f4add(float4 a, float4 b) {
    return make_float4(a.x + b.x, a.y + b.y, a.z + b.z, a.w + b.w);
}
__device__ __forceinline__ float4 f4sub(float4 a, float4 b) {
    return make_float4(a.x - b.x, a.y - b.y, a.z - b.z, a.w - b.w);
}

// ---------------------------------------------------------------------------
// K1 (fused): streaming patch-sum reduction + per-batch routing tail.
// Grid = (chunk, batch) -- x = chunk FASTEST, so each batch's 14 blocks are
// contiguous in bid: batches complete in staggered order and the routing
// tails overlap with later batches' streaming (the R7 failure had the axes
// swapped, clustering all 64 tails at the end).
// Block: 256 threads = 64 channel-quads x 4 row-threads; each row-thread owns
// one row (even/odd running float4 sums + edge captures -> dw-class sums).
// Reducer (rt==0) applies h-parity/boundary logic, stores 9 slots to scratch.
// The LAST block of each batch (fence+atomic counter) sums the 14 chunk
// partials, runs the 2304x64 pooled GEMM, dense(4), argmax -> route + logits.
// ---------------------------------------------------------------------------
__global__ __launch_bounds__(256) void patch_route_kernel(const float* __restrict__ in,
                                                          const float* __restrict__ conv_w,
                                                          const float* __restrict__ conv_b,
                                                          const float* __restrict__ fc_w,
                                                          const float* __restrict__ fc_b,
                                                          float* __restrict__ out_logits) {
    const int chunk = blockIdx.x;          // 0..13  (fastest -> staggered batches)
    const int b     = blockIdx.y;          // 0..63
    const int tid   = threadIdx.x;
    const int q     = tid & 63;            // channel quad 0..63
    const int rt    = tid >> 6;            // row-thread 0..3
    const int h     = chunk * 4 + rt;

    const float4* row = (const float4*)in
                      + ((size_t)(b * HH + h) * WW) * (CC / 4) + q;

    float4 e = make_float4(0.f, 0.f, 0.f, 0.f);
    float4 o = make_float4(0.f, 0.f, 0.f, 0.f);
    float4 v0, v54, v55;
#pragma unroll
    for (int w = 0; w < WW; w += 2) {
        float4 a  = row[(size_t)w * (CC / 4)];
        float4 bb = row[(size_t)(w + 1) * (CC / 4)];
        if (w == 0)  { v0 = a; }
        if (w == 54) { v54 = a; v55 = bb; }
        e = f4add(e, a);
        o = f4add(o, bb);
    }

    __shared__ float4 sacc[4][3][64];
    sacc[rt][0][q] = f4sub(e, v54);  // W0: even w in [0,52]
    sacc[rt][1][q] = f4sub(o, v55);  // W1: odd  w in [1,53]
    sacc[rt][2][q] = f4sub(e, v0);   // W2: even w in [2,54]
    __syncthreads();

    if (rt == 0) {
        float4 out[SLOTS];
#pragma unroll
        for (int s = 0; s < SLOTS; s++) out[s] = make_float4(0.f, 0.f, 0.f, 0.f);

#pragma unroll
        for (int r = 0; r < 4; r++) {
            const int hh = chunk * 4 + r;
            const float4 W0 = sacc[r][0][q];
            const float4 W1 = sacc[r][1][q];
            const float4 W2 = sacc[r][2][q];
            if ((hh & 1) == 0) {
                if (hh <= 52) { out[0] = f4add(out[0], W0); out[1] = f4add(out[1], W1); out[2] = f4add(out[2], W2); }
                if (hh >= 2)  { out[6] = f4add(out[6], W0); out[7] = f4add(out[7], W1); out[8] = f4add(out[8], W2); }
            } else {
                if (hh <= 53) { out[3] = f4add(out[3], W0); out[4] = f4add(out[4], W1); out[5] = f4add(out[5], W2); }
            }
        }

        float4* dst = (float4*)g_S2 + ((size_t)(b * RCHUNKS + chunk) * SLOTS) * (CC / 4) + q;
#pragma unroll
        for (int s = 0; s < SLOTS; s++)
            dst[(size_t)s * (CC / 4)] = out[s];
    }
    __syncthreads();

    // ---- per-batch completion counter; only the last block proceeds --------
    __shared__ int s_last;
    if (tid == 0) {
        __threadfence();                           // publish g_S2 stores
        int old = atomicAdd(&g_cnt[b], 1);
        s_last = (old == RCHUNKS - 1);
        if (s_last) g_cnt[b] = 0;                  // reset for next graph replay
    }
    __syncthreads();
    if (!s_last) return;
    if (tid == 0) __threadfence();                 // acquire side
    __syncthreads();

    // ---- tail: sum 14 chunk-partials -> sS(2304) ---------------------------
    __shared__ __align__(16) float sS[SLOTS * CC];
    for (int i = tid; i < SLOTS * CC / 4; i += 256) {
        float4 s = make_float4(0.f, 0.f, 0.f, 0.f);
#pragma unroll
        for (int k = 0; k < RCHUNKS; k++) {
            const float4* src = (const float4*)g_S2
                              + (size_t)(b * RCHUNKS + k) * (SLOTS * CC / 4) + i;
            s = f4add(s, __ldcg(src));             // L2 read (cross-SM producer)
        }
        ((float4*)sS)[i] = s;
    }
    __syncthreads();

    // ---- pooled GEMM: 4 sub-segments of 576 per output ---------------------
    const int oc  = tid & 63;
    const int sub = tid >> 6;
    const int j0  = sub * 576;

    float acc = 0.f;
#pragma unroll 8
    for (int j = 0; j < 576; j++)
        acc = fmaf(sS[j0 + j], conv_w[(size_t)(j0 + j) * COUT + oc], acc);

    __shared__ float part[4][COUT];
    part[sub][oc] = acc;
    __syncthreads();

    __shared__ float sp[COUT];
    __shared__ float slog[ROUTES];
    if (tid < COUT) {
        sp[tid] = (part[0][tid] + part[1][tid] + part[2][tid] + part[3][tid])
                  * (1.0f / 729.0f) + conv_b[tid];
    }
    __syncthreads();

    if (tid < ROUTES) {
        float l = fc_b[tid];
#pragma unroll
        for (int j = 0; j < COUT; j++)
            l = fmaf(sp[j], fc_w[j * ROUTES + tid], l);
        slog[tid] = l;
        out_logits[b * ROUTES + tid] = l;
    }
    __syncthreads();

    if (tid == 0) {
        float best = slog[0];
        int br = 0;
#pragma unroll
        for (int r = 1; r < ROUTES; r++)
            if (slog[r] > best) { best = slog[r]; br = r; }  // first-max == argmax
        g_route[b] = br;
    }
}

// ---------------------------------------------------------------------------
// K3: routed channel-group gather (measured-best config, at its traffic floor).
// Block = (batch, 64-pixel tile), 4 independent float4 copies per thread.
// ---------------------------------------------------------------------------
__global__ __launch_bounds__(256) void gather_kernel(const float4* __restrict__ in4,
                                                     float4* __restrict__ out4) {
    const int b = blockIdx.x;
    const int r = g_route[b];
    const size_t base_pix = (size_t)b * (HH * WW) + (size_t)blockIdx.y * 64;
    const float4* src = in4 + base_pix * (CC / 4) + r * (RW / 4);
    float4* dst = out4 + base_pix * (RW / 4);

    const int t = threadIdx.x;
#pragma unroll
    for (int k = 0; k < 4; k++) {
        const int item = t + k * 256;      // 0..1023 = 64 pixels x 16 float4
        const int p = item >> 4;
        const int j = item & 15;
        dst[item] = src[(size_t)p * (CC / 4) + j];
    }
}

// ---------------------------------------------------------------------------
extern "C" void kernel_launch(void* const* d_in, const int* in_sizes, int n_in,
                              void* d_out, int out_size) {
    const float* in     = (const float*)d_in[0];
    const float* conv_w = (const float*)d_in[1];
    const float* conv_b = (const float*)d_in[2];
    const float* fc_w   = (const float*)d_in[3];
    const float* fc_b   = (const float*)d_in[4];

    float* out        = (float*)d_out;
    float* out_logits = out + (size_t)BB * HH * WW * RW;  // x first, then logits

    patch_route_kernel<<<dim3(RCHUNKS, BB), 256>>>(in, conv_w, conv_b, fc_w, fc_b, out_logits);
    gather_kernel<<<dim3(BB, HH * WW / 64), 256>>>((const float4*)in, (float4*)out);
}